// round 11
// baseline (speedup 1.0000x reference)
#include <cuda_runtime.h>
#include <cuda_fp16.h>
#include <cstdint>

// CGC layer — fp16 mma.sync with f16 accumulate per K=32 chunk, promoted to
// f32 each k-tile (2x HMMA throughput vs f32-acc path, bounded error).
// 128x128 CTA tile, 2 CTAs/SM, 4-stage cp.async, single barrier per k-tile.
// Inputs: x(8192,1024) Ws(4,1024,1024) bs(4,1024) Wt(3,4,1024,1024) bt(3,4,1024) Wg(3,1024,8)
// Output: mixture (3, 8192, 1024) f32

#define BATCH 8192
#define DM    1024
#define HD    1024
#define NTASK 3

__device__ __half g_yh[16ull * BATCH * HD];        // 256 MB expert outputs (fp16)
__device__ float  g_gates[NTASK * BATCH * 8];
__device__ __half g_xh[(size_t)BATCH * DM];        // 16 MB x fp16 [b][k]
__device__ __half g_wh[16ull * DM * HD];           // 32 MB W fp16 transposed [e][n][k]

// ---------------------------------------------------------------------------
// helpers
// ---------------------------------------------------------------------------
__device__ __forceinline__ uint32_t smem_u32(const void* p) {
    uint32_t a;
    asm("{ .reg .u64 t; cvta.to.shared.u64 t, %1; cvt.u32.u64 %0, t; }" : "=r"(a) : "l"(p));
    return a;
}
__device__ __forceinline__ void cp_async16(uint32_t dst, const void* src) {
    asm volatile("cp.async.cg.shared.global [%0], [%1], 16;\n" :: "r"(dst), "l"(src) : "memory");
}
__device__ __forceinline__ void cp_commit() {
    asm volatile("cp.async.commit_group;\n" ::: "memory");
}
template <int N>
__device__ __forceinline__ void cp_wait_group() {
    asm volatile("cp.async.wait_group %0;\n" :: "n"(N) : "memory");
}
// f16-accumulate MMA: D(f16x2 x2) = A*B + C
__device__ __forceinline__ void mma_f16acc(uint32_t* d, const uint32_t* a,
                                           const uint32_t* b,
                                           uint32_t c0, uint32_t c1) {
    asm volatile(
        "mma.sync.aligned.m16n8k16.row.col.f16.f16.f16.f16 "
        "{%0,%1}, {%2,%3,%4,%5}, {%6,%7}, {%8,%9};"
        : "=r"(d[0]), "=r"(d[1])
        : "r"(a[0]), "r"(a[1]), "r"(a[2]), "r"(a[3]),
          "r"(b[0]), "r"(b[1]), "r"(c0), "r"(c1));
}
__device__ __forceinline__ void ldsm_x4(uint32_t* r, uint32_t addr) {
    asm volatile("ldmatrix.sync.aligned.m8n8.x4.shared.b16 {%0,%1,%2,%3}, [%4];"
        : "=r"(r[0]), "=r"(r[1]), "=r"(r[2]), "=r"(r[3]) : "r"(addr));
}

// ---------------------------------------------------------------------------
// K0a: x fp32 -> fp16
// ---------------------------------------------------------------------------
__global__ __launch_bounds__(256) void cvt_x(const float* __restrict__ src,
                                             __half* __restrict__ dst)
{
    const size_t i = ((size_t)blockIdx.x * blockDim.x + threadIdx.x) * 8;
    float4 v0 = *(const float4*)(src + i);
    float4 v1 = *(const float4*)(src + i + 4);
    __half2 h[4];
    h[0] = __floats2half2_rn(v0.x, v0.y);
    h[1] = __floats2half2_rn(v0.z, v0.w);
    h[2] = __floats2half2_rn(v1.x, v1.y);
    h[3] = __floats2half2_rn(v1.z, v1.w);
    *(uint4*)(dst + i) = *(uint4*)h;
}

// ---------------------------------------------------------------------------
// K0b: W fp32 [e][k][n] -> fp16 transposed [e][n][k]
// ---------------------------------------------------------------------------
__global__ __launch_bounds__(256) void cvt_w(const float* __restrict__ Ws,
                                             const float* __restrict__ Wt)
{
    __shared__ float t[32][33];
    const int e = blockIdx.z;
    const float* src = (e < 4) ? Ws + (size_t)e * DM * HD
                               : Wt + (size_t)(e - 4) * DM * HD;
    const int n0 = blockIdx.x * 32;
    const int k0 = blockIdx.y * 32;
    const int tx = threadIdx.x & 31;
    const int ty = threadIdx.x >> 5;

    #pragma unroll
    for (int i = 0; i < 32; i += 8)
        t[ty + i][tx] = src[(size_t)(k0 + ty + i) * HD + n0 + tx];
    __syncthreads();
    __half* dst = g_wh + (size_t)e * DM * HD;
    #pragma unroll
    for (int i = 0; i < 32; i += 8)
        dst[(size_t)(n0 + ty + i) * DM + k0 + tx] = __float2half_rn(t[tx][ty + i]);
}

// ---------------------------------------------------------------------------
// K1: gate logits + softmax. 256 blocks x 32 rows; Wg staged in smem once.
// ---------------------------------------------------------------------------
#define GATE_ROWS 32
#define GATE_SMEM (NTASK * DM * 8 * 4)   // 98304 bytes

__global__ __launch_bounds__(256) void gate_kernel(const float* __restrict__ x,
                                                   const float* __restrict__ Wg)
{
    extern __shared__ float wgs[];       // [3][1024][8]
    const int tid = threadIdx.x;

    for (int i = tid; i < NTASK * DM * 8 / 4; i += 256)
        ((float4*)wgs)[i] = ((const float4*)Wg)[i];
    __syncthreads();

    const int w    = tid >> 5;
    const int lane = tid & 31;
    const int b0   = blockIdx.x * GATE_ROWS;

    for (int i = w; i < GATE_ROWS * NTASK; i += 8) {
        const int row = i & 31;
        const int t   = i >> 5;
        const float* xr = x + (size_t)(b0 + row) * DM;
        const float* wt = wgs + (size_t)t * DM * 8;

        float acc[8] = {0.f, 0.f, 0.f, 0.f, 0.f, 0.f, 0.f, 0.f};
        for (int d = lane; d < DM; d += 32) {
            const float xv = xr[d];
            float4 w0 = *(const float4*)(wt + (size_t)d * 8);
            float4 w1 = *(const float4*)(wt + (size_t)d * 8 + 4);
            acc[0] = fmaf(xv, w0.x, acc[0]);
            acc[1] = fmaf(xv, w0.y, acc[1]);
            acc[2] = fmaf(xv, w0.z, acc[2]);
            acc[3] = fmaf(xv, w0.w, acc[3]);
            acc[4] = fmaf(xv, w1.x, acc[4]);
            acc[5] = fmaf(xv, w1.y, acc[5]);
            acc[6] = fmaf(xv, w1.z, acc[6]);
            acc[7] = fmaf(xv, w1.w, acc[7]);
        }
        #pragma unroll
        for (int off = 16; off > 0; off >>= 1) {
            #pragma unroll
            for (int j = 0; j < 8; j++)
                acc[j] += __shfl_down_sync(0xffffffffu, acc[j], off);
        }
        if (lane == 0) {
            float m = acc[0];
            #pragma unroll
            for (int j = 1; j < 8; j++) m = fmaxf(m, acc[j]);
            float e[8], s = 0.f;
            #pragma unroll
            for (int j = 0; j < 8; j++) { e[j] = expf(acc[j] - m); s += e[j]; }
            float inv = 1.f / s;
            float* gp = g_gates + ((size_t)t * BATCH + (b0 + row)) * 8;
            #pragma unroll
            for (int j = 0; j < 8; j++) gp[j] = e[j] * inv;
        }
    }
}

// ---------------------------------------------------------------------------
// K2: fp16 mma (f16 accumulate per K=32, f32 promotion per k-tile).
// 128x128x32 CTA tile, 8 warps (2m x 4n), 64x32 warp tiles, 4-stage cp.async,
// ONE barrier per k-tile, 2 CTAs/SM.
// ---------------------------------------------------------------------------
#define STAGES      4
#define A_STRIDE_H  40
#define B_STRIDE_H  40
#define A_BYTES_H   (128 * A_STRIDE_H * 2)   // 10240
#define B_BYTES_H   (128 * B_STRIDE_H * 2)   // 10240
#define STAGE_H     (A_BYTES_H + B_BYTES_H)  // 20480
#define SMEM_GEMM   (STAGES * STAGE_H + 512) // 82432

__global__ __launch_bounds__(256, 2) void expert_gemm_f16(const float* __restrict__ bs,
                                                          const float* __restrict__ bt)
{
    extern __shared__ char smem[];
    const uint32_t sbase = smem_u32(smem);
    float* biassm = (float*)(smem + STAGES * STAGE_H);

    const int tid  = threadIdx.x;
    const int w    = tid >> 5;
    const int lane = tid & 31;
    const int gid  = lane >> 2;
    const int tig  = lane & 3;
    const int warp_m = (w >> 2) * 64;   // 0,64
    const int warp_n = (w & 3) * 32;    // 0,32,64,96

    const int e  = blockIdx.z;
    const int n0 = blockIdx.x * 128;
    const int m0 = blockIdx.y * 128;

    const __half* W   = g_wh + (size_t)e * DM * HD;      // [n][k]
    const float* bias = (e < 4) ? bs + (size_t)e * HD : bt + (size_t)(e - 4) * HD;
    __half* Y = g_yh + (size_t)e * BATCH * HD;

    if (tid < 128) biassm[tid] = bias[n0 + tid];

    const uint32_t a_lane_off =
        (uint32_t)((warp_m + (lane & 7) + ((lane >> 3) & 1) * 8) * A_STRIDE_H
                   + (lane >> 4) * 8) * 2;
    const uint32_t b_lane_off =
        (uint32_t)(A_BYTES_H) +
        (uint32_t)((warp_n + (lane & 7) + (lane >> 4) * 8) * B_STRIDE_H
                   + ((lane >> 3) & 1) * 8) * 2;

    float c[4][4][4];
    #pragma unroll
    for (int mi = 0; mi < 4; mi++)
        #pragma unroll
        for (int ni = 0; ni < 4; ni++)
            #pragma unroll
            for (int r = 0; r < 4; r++) c[mi][ni][r] = 0.f;

    auto load_stage = [&](int s, int kt) {
        const uint32_t ab = sbase + (uint32_t)s * STAGE_H;
        const uint32_t bb = ab + A_BYTES_H;
        const int kbase = kt * 32;
        #pragma unroll
        for (int i = 0; i < 2; i++) {
            const int idx = tid + i * 256;
            const int row = idx >> 2, q = idx & 3;
            cp_async16(ab + (uint32_t)(row * 80 + q * 16),
                       g_xh + (size_t)(m0 + row) * DM + kbase + q * 8);
        }
        #pragma unroll
        for (int i = 0; i < 2; i++) {
            const int idx = tid + i * 256;
            const int row = idx >> 2, q = idx & 3;
            cp_async16(bb + (uint32_t)(row * 80 + q * 16),
                       W + (size_t)(n0 + row) * DM + kbase + q * 8);
        }
        cp_commit();
    };

    load_stage(0, 0);
    load_stage(1, 1);
    load_stage(2, 2);

    for (int kt = 0; kt < 32; kt++) {
        if (kt < 30)       cp_wait_group<2>();
        else if (kt == 30) cp_wait_group<1>();
        else               cp_wait_group<0>();
        __syncthreads();

        if (kt + 3 < 32) load_stage((kt + 3) % STAGES, kt + 3);

        const uint32_t stage = sbase + (uint32_t)(kt % STAGES) * STAGE_H;
        const uint32_t a_base = stage + a_lane_off;
        const uint32_t b_base = stage + b_lane_off;

        // B fragments for both k16 slices up front (4 ldsm, 16 regs)
        uint32_t b[2][4][2];
        #pragma unroll
        for (int ks = 0; ks < 2; ks++) {
            const uint32_t koff = (uint32_t)(ks * 32);
            uint32_t r[4];
            ldsm_x4(r, b_base + koff);                                   // n 0..15
            b[ks][0][0] = r[0]; b[ks][0][1] = r[1];
            b[ks][1][0] = r[2]; b[ks][1][1] = r[3];
            ldsm_x4(r, b_base + (uint32_t)(16 * B_STRIDE_H) * 2 + koff); // n 16..31
            b[ks][2][0] = r[0]; b[ks][2][1] = r[1];
            b[ks][3][0] = r[2]; b[ks][3][1] = r[3];
        }

        #pragma unroll
        for (int mi = 0; mi < 4; mi++) {
            uint32_t a0[4], a1[4];
            const uint32_t am = a_base + (uint32_t)(mi * 16 * A_STRIDE_H) * 2;
            ldsm_x4(a0, am);        // ks0
            ldsm_x4(a1, am + 32);   // ks1
            #pragma unroll
            for (int ni = 0; ni < 4; ni++) {
                uint32_t d[2];
                mma_f16acc(d, a0, b[0][ni], 0u, 0u);       // C = 0
                mma_f16acc(d, a1, b[1][ni], d[0], d[1]);   // chain in f16
                const float2 lo = __half22float2(*(const __half2*)&d[0]);
                const float2 hi = __half22float2(*(const __half2*)&d[1]);
                c[mi][ni][0] += lo.x;
                c[mi][ni][1] += lo.y;
                c[mi][ni][2] += hi.x;
                c[mi][ni][3] += hi.y;
            }
        }
    }

    // epilogue: bias + relu -> fp16 stores
    #pragma unroll
    for (int mi = 0; mi < 4; mi++) {
        #pragma unroll
        for (int ni = 0; ni < 4; ni++) {
            const int rbase = m0 + warp_m + mi * 16 + gid;
            const int col   = warp_n + ni * 8 + 2 * tig;
            const float b0 = biassm[col], b1 = biassm[col + 1];
            __half2 p0 = __floats2half2_rn(fmaxf(c[mi][ni][0] + b0, 0.f),
                                           fmaxf(c[mi][ni][1] + b1, 0.f));
            __half2 p1 = __floats2half2_rn(fmaxf(c[mi][ni][2] + b0, 0.f),
                                           fmaxf(c[mi][ni][3] + b1, 0.f));
            *(__half2*)(Y + (size_t)rbase * HD + n0 + col)       = p0;
            *(__half2*)(Y + (size_t)(rbase + 8) * HD + n0 + col) = p1;
        }
    }
}

// ---------------------------------------------------------------------------
// K3: gated mixture — all 3 tasks per thread (shared experts loaded once).
// ---------------------------------------------------------------------------
__global__ __launch_bounds__(256) void mix_kernel(float* __restrict__ out)
{
    const size_t idx = (size_t)blockIdx.x * blockDim.x + threadIdx.x;  // (b,h4)
    const int h4 = (int)(idx & 255);
    const int b  = (int)(idx >> 8);

    float g[NTASK][8];
    #pragma unroll
    for (int t = 0; t < NTASK; t++) {
        const float4* gp = (const float4*)(g_gates + ((size_t)t * BATCH + b) * 8);
        float4 g0 = gp[0], g1 = gp[1];
        g[t][0] = g0.x; g[t][1] = g0.y; g[t][2] = g0.z; g[t][3] = g0.w;
        g[t][4] = g1.x; g[t][5] = g1.y; g[t][6] = g1.z; g[t][7] = g1.w;
    }

    float4 acc[NTASK];
    #pragma unroll
    for (int t = 0; t < NTASK; t++) acc[t] = make_float4(0.f, 0.f, 0.f, 0.f);

    // shared experts (y indices 0..3): contribute to all tasks at gate slot 4+j
    #pragma unroll
    for (int j = 0; j < 4; j++) {
        const uint2 v = *(const uint2*)(g_yh + ((size_t)j * BATCH + b) * HD + (size_t)h4 * 4);
        const float2 f01 = __half22float2(*(const __half2*)&v.x);
        const float2 f23 = __half22float2(*(const __half2*)&v.y);
        #pragma unroll
        for (int t = 0; t < NTASK; t++) {
            const float gv = g[t][4 + j];
            acc[t].x = fmaf(gv, f01.x, acc[t].x);
            acc[t].y = fmaf(gv, f01.y, acc[t].y);
            acc[t].z = fmaf(gv, f23.x, acc[t].z);
            acc[t].w = fmaf(gv, f23.y, acc[t].w);
        }
    }
    // task-specific experts (y indices 4 + t*4 + j): gate slot j
    #pragma unroll
    for (int t = 0; t < NTASK; t++) {
        #pragma unroll
        for (int j = 0; j < 4; j++) {
            const int ei = 4 + t * 4 + j;
            const uint2 v = *(const uint2*)(g_yh + ((size_t)ei * BATCH + b) * HD + (size_t)h4 * 4);
            const float2 f01 = __half22float2(*(const __half2*)&v.x);
            const float2 f23 = __half22float2(*(const __half2*)&v.y);
            const float gv = g[t][j];
            acc[t].x = fmaf(gv, f01.x, acc[t].x);
            acc[t].y = fmaf(gv, f01.y, acc[t].y);
            acc[t].z = fmaf(gv, f23.x, acc[t].z);
            acc[t].w = fmaf(gv, f23.y, acc[t].w);
        }
    }

    #pragma unroll
    for (int t = 0; t < NTASK; t++)
        *(float4*)(out + ((size_t)t * BATCH + b) * HD + (size_t)h4 * 4) = acc[t];
}

// ---------------------------------------------------------------------------
extern "C" void kernel_launch(void* const* d_in, const int* in_sizes, int n_in,
                              void* d_out, int out_size)
{
    (void)in_sizes; (void)n_in; (void)out_size;
    const float* x  = (const float*)d_in[0];
    const float* Ws = (const float*)d_in[1];
    const float* bs = (const float*)d_in[2];
    const float* Wt = (const float*)d_in[3];
    const float* bt = (const float*)d_in[4];
    const float* Wg = (const float*)d_in[5];
    float* out = (float*)d_out;

    cudaFuncSetAttribute(expert_gemm_f16,
                         cudaFuncAttributeMaxDynamicSharedMemorySize, SMEM_GEMM);
    cudaFuncSetAttribute(gate_kernel,
                         cudaFuncAttributeMaxDynamicSharedMemorySize, GATE_SMEM);

    {
        __half* xh = nullptr;
        cudaGetSymbolAddress((void**)&xh, g_xh);
        cvt_x<<<(unsigned)((size_t)BATCH * DM / 8 / 256), 256>>>(x, xh);
        cvt_w<<<dim3(32, 32, 16), 256>>>(Ws, Wt);
    }

    gate_kernel<<<BATCH / GATE_ROWS, 256, GATE_SMEM>>>(x, Wg);
    expert_gemm_f16<<<dim3(8, 64, 16), 256, SMEM_GEMM>>>(bs, bt);

    const size_t nthreads = (size_t)BATCH * (HD / 4);
    mix_kernel<<<(unsigned)(nthreads / 256), 256>>>(out);
}

// round 12
// speedup vs baseline: 1.5460x; 1.5460x over previous
#include <cuda_runtime.h>
#include <cuda_fp16.h>
#include <cstdint>

// CGC layer — fp16 mma.sync (f32 acc) + cp.async.bulk stage loads from
// pre-packed, pre-swizzled global tiles. 128x128 CTA tile, 2 CTAs/SM,
// 4-stage mbarrier pipeline, 1 barrier per k-tile.
// Inputs: x(8192,1024) Ws(4,1024,1024) bs(4,1024) Wt(3,4,1024,1024) bt(3,4,1024) Wg(3,1024,8)
// Output: mixture (3, 8192, 1024) f32

#define BATCH 8192
#define DM    1024
#define HD    1024
#define NTASK 3

// packed tile: 128 rows x 32 k fp16 = 8192 B; row r holds 4 16B-chunks,
// chunk c stored at byte r*64 + ((c ^ ((r>>1)&3)) * 16)   (XOR swizzle)
#define TILE_B 8192

__device__ __half g_yh[16ull * BATCH * HD];                 // 256 MB expert outputs
__device__ float  g_gates[NTASK * BATCH * 8];
__device__ __align__(128) unsigned char g_xp[64ull * 32 * TILE_B];       // 16 MB packed x
__device__ __align__(128) unsigned char g_wp[16ull * 8 * 32 * TILE_B];   // 32 MB packed W^T

// ---------------------------------------------------------------------------
// helpers
// ---------------------------------------------------------------------------
__device__ __forceinline__ uint32_t smem_u32(const void* p) {
    uint32_t a;
    asm("{ .reg .u64 t; cvta.to.shared.u64 t, %1; cvt.u32.u64 %0, t; }" : "=r"(a) : "l"(p));
    return a;
}
__device__ __forceinline__ void mma_f16(float* c, const uint32_t* a, const uint32_t* b) {
    asm volatile(
        "mma.sync.aligned.m16n8k16.row.col.f32.f16.f16.f32 "
        "{%0,%1,%2,%3}, {%4,%5,%6,%7}, {%8,%9}, {%0,%1,%2,%3};"
        : "+f"(c[0]), "+f"(c[1]), "+f"(c[2]), "+f"(c[3])
        : "r"(a[0]), "r"(a[1]), "r"(a[2]), "r"(a[3]), "r"(b[0]), "r"(b[1]));
}
__device__ __forceinline__ void ldsm_x4(uint32_t* r, uint32_t addr) {
    asm volatile("ldmatrix.sync.aligned.m8n8.x4.shared.b16 {%0,%1,%2,%3}, [%4];"
        : "=r"(r[0]), "=r"(r[1]), "=r"(r[2]), "=r"(r[3]) : "r"(addr));
}
__device__ __forceinline__ void bulk_g2s(uint32_t dst, const void* src,
                                         uint32_t bytes, uint32_t mbar) {
    asm volatile(
        "cp.async.bulk.shared::cluster.global.mbarrier::complete_tx::bytes "
        "[%0], [%1], %2, [%3];"
        :: "r"(dst), "l"(src), "r"(bytes), "r"(mbar) : "memory");
}
#define MBARRIER_INIT(mbar, count) \
    asm volatile("mbarrier.init.shared.b64 [%0], %1;" \
                 :: "r"((uint32_t)(mbar)), "r"((uint32_t)(count)) : "memory")
#define MBARRIER_EXPECT_TX(mbar, tx) \
    asm volatile("mbarrier.arrive.expect_tx.shared.b64 _, [%0], %1;" \
                 :: "r"((uint32_t)(mbar)), "r"((uint32_t)(tx)) : "memory")
#define MBARRIER_WAIT_PARITY(mbar, par) do { \
    uint32_t _m = (uint32_t)(mbar), _p = (uint32_t)(par), _d; \
    asm volatile( \
        "{\n\t.reg .pred p;\n\t" \
        "mbarrier.try_wait.parity.acquire.cta.shared::cta.b64 p, [%1], %2;\n\t" \
        "selp.b32 %0, 1, 0, p;\n\t}" \
        : "=r"(_d) : "r"(_m), "r"(_p) : "memory"); \
    if (!_d) { \
        asm volatile( \
            "{\n\t.reg .pred P1;\n\t" \
            "WL_%=:\n\t" \
            "mbarrier.try_wait.parity.acquire.cta.shared::cta.b64 P1, [%0], %1, 0x989680;\n\t" \
            "@P1 bra.uni WD_%=;\n\t" \
            "bra.uni WL_%=;\n\t" \
            "WD_%=:\n\t}" \
            :: "r"(_m), "r"(_p) : "memory"); \
    } \
} while (0)

// ---------------------------------------------------------------------------
// K0a: pack x -> g_xp  (fp32 -> fp16, tiled + swizzled)
// ---------------------------------------------------------------------------
__global__ __launch_bounds__(256) void pack_x(const float* __restrict__ x)
{
    const uint32_t idx = blockIdx.x * 256 + threadIdx.x;   // 1,048,576 chunks
    const uint32_t mb = idx >> 14;
    const uint32_t rem = idx & 16383;
    const uint32_t kt = rem >> 9;
    const uint32_t t  = rem & 511;
    const uint32_t r  = t >> 2, c = t & 3;

    const float* src = x + ((size_t)mb * 128 + r) * DM + kt * 32 + c * 8;
    float4 v0 = *(const float4*)src;
    float4 v1 = *(const float4*)(src + 4);
    __half2 h[4];
    h[0] = __floats2half2_rn(v0.x, v0.y);
    h[1] = __floats2half2_rn(v0.z, v0.w);
    h[2] = __floats2half2_rn(v1.x, v1.y);
    h[3] = __floats2half2_rn(v1.z, v1.w);

    unsigned char* dst = g_xp + ((size_t)mb * 32 + kt) * TILE_B
                       + r * 64 + ((c ^ ((r >> 1) & 3)) << 4);
    *(uint4*)dst = *(uint4*)h;
}

// ---------------------------------------------------------------------------
// K0b: pack W -> g_wp  (fp32 [e][k][n] -> fp16 [e][nb][kt] tiles, swizzled)
// ---------------------------------------------------------------------------
__global__ __launch_bounds__(256) void pack_w(const float* __restrict__ Ws,
                                              const float* __restrict__ Wt)
{
    __shared__ float t[32][33];
    const int e  = blockIdx.z;
    const float* src = (e < 4) ? Ws + (size_t)e * DM * HD
                               : Wt + (size_t)(e - 4) * DM * HD;
    const int n0 = blockIdx.x * 32;
    const int k0 = blockIdx.y * 32;
    const int tx = threadIdx.x & 31;
    const int ty = threadIdx.x >> 5;

    #pragma unroll
    for (int i = 0; i < 32; i += 8)
        t[ty + i][tx] = src[(size_t)(k0 + ty + i) * HD + n0 + tx];   // t[k][n]
    __syncthreads();

    if (threadIdx.x < 128) {
        const int rl = threadIdx.x >> 2;     // 0..31 local n-row
        const int c  = threadIdx.x & 3;      // chunk
        const int rr = (n0 & 127) + rl;      // row within 128-row tile
        const int nb = n0 >> 7;
        const int kt = k0 >> 5;

        __half2 h[4];
        #pragma unroll
        for (int j = 0; j < 4; j++)
            h[j] = __floats2half2_rn(t[c * 8 + j * 2][rl], t[c * 8 + j * 2 + 1][rl]);

        unsigned char* dst = g_wp + (((size_t)e * 8 + nb) * 32 + kt) * TILE_B
                           + rr * 64 + ((c ^ ((rr >> 1) & 3)) << 4);
        *(uint4*)dst = *(uint4*)h;
    }
}

// ---------------------------------------------------------------------------
// K1: gate logits + softmax (Wg staged in smem)
// ---------------------------------------------------------------------------
#define GATE_ROWS 32
#define GATE_SMEM (NTASK * DM * 8 * 4)

__global__ __launch_bounds__(256) void gate_kernel(const float* __restrict__ x,
                                                   const float* __restrict__ Wg)
{
    extern __shared__ float wgs[];
    const int tid = threadIdx.x;

    for (int i = tid; i < NTASK * DM * 8 / 4; i += 256)
        ((float4*)wgs)[i] = ((const float4*)Wg)[i];
    __syncthreads();

    const int w    = tid >> 5;
    const int lane = tid & 31;
    const int b0   = blockIdx.x * GATE_ROWS;

    for (int i = w; i < GATE_ROWS * NTASK; i += 8) {
        const int row = i & 31;
        const int t   = i >> 5;
        const float* xr = x + (size_t)(b0 + row) * DM;
        const float* wt = wgs + (size_t)t * DM * 8;

        float acc[8] = {0.f, 0.f, 0.f, 0.f, 0.f, 0.f, 0.f, 0.f};
        for (int d = lane; d < DM; d += 32) {
            const float xv = xr[d];
            float4 w0 = *(const float4*)(wt + (size_t)d * 8);
            float4 w1 = *(const float4*)(wt + (size_t)d * 8 + 4);
            acc[0] = fmaf(xv, w0.x, acc[0]);
            acc[1] = fmaf(xv, w0.y, acc[1]);
            acc[2] = fmaf(xv, w0.z, acc[2]);
            acc[3] = fmaf(xv, w0.w, acc[3]);
            acc[4] = fmaf(xv, w1.x, acc[4]);
            acc[5] = fmaf(xv, w1.y, acc[5]);
            acc[6] = fmaf(xv, w1.z, acc[6]);
            acc[7] = fmaf(xv, w1.w, acc[7]);
        }
        #pragma unroll
        for (int off = 16; off > 0; off >>= 1) {
            #pragma unroll
            for (int j = 0; j < 8; j++)
                acc[j] += __shfl_down_sync(0xffffffffu, acc[j], off);
        }
        if (lane == 0) {
            float m = acc[0];
            #pragma unroll
            for (int j = 1; j < 8; j++) m = fmaxf(m, acc[j]);
            float e[8], s = 0.f;
            #pragma unroll
            for (int j = 0; j < 8; j++) { e[j] = expf(acc[j] - m); s += e[j]; }
            float inv = 1.f / s;
            float* gp = g_gates + ((size_t)t * BATCH + (b0 + row)) * 8;
            #pragma unroll
            for (int j = 0; j < 8; j++) gp[j] = e[j] * inv;
        }
    }
}

// ---------------------------------------------------------------------------
// K2: expert GEMM. 128x128x32 CTA tile, 8 warps (2m x 4n), 64x32 warp tiles,
// 4-stage cp.async.bulk pipeline with mbarriers, 2 CTAs/SM.
// SMEM: 4 stages x (A 8KB + B 8KB) = 65536, mbarriers @65536, bias @65600.
// ---------------------------------------------------------------------------
#define STAGE_B   (2 * TILE_B)         // 16384
#define SMEM_MBAR 65536
#define SMEM_BIAS 65600
#define SMEM_GEMM (SMEM_BIAS + 512)    // 66112

__global__ __launch_bounds__(256, 2) void expert_gemm_f16(const float* __restrict__ bs,
                                                          const float* __restrict__ bt)
{
    extern __shared__ char smem[];
    const uint32_t sbase = smem_u32(smem);
    float* biassm = (float*)(smem + SMEM_BIAS);

    const int tid  = threadIdx.x;
    const int w    = tid >> 5;
    const int lane = tid & 31;
    const int gid  = lane >> 2;
    const int tig  = lane & 3;
    const int warp_m = (w >> 2) * 64;   // 0,64
    const int warp_n = (w & 3) * 32;    // 0,32,64,96

    const int e  = blockIdx.z;
    const int nb = blockIdx.x;          // 0..7
    const int mb = blockIdx.y;          // 0..63
    const int n0 = nb * 128;
    const int m0 = mb * 128;

    const unsigned char* Ax = g_xp + (size_t)mb * 32 * TILE_B;
    const unsigned char* Bw = g_wp + ((size_t)e * 8 + nb) * 32 * TILE_B;
    const float* bias = (e < 4) ? bs + (size_t)e * HD : bt + (size_t)(e - 4) * HD;
    __half* Y = g_yh + (size_t)e * BATCH * HD;

    if (tid < 128) biassm[tid] = bias[n0 + tid];

    // precompute swizzled ldsm lane offsets (within a stage)
    uint32_t off_a[4][2], off_b[2][2];
    {
        const int hi_a = lane >> 4;              // A chunk-high selector
        #pragma unroll
        for (int mi = 0; mi < 4; mi++) {
            const int row = warp_m + mi * 16 + (lane & 7) + ((lane >> 3) & 1) * 8;
            const int sw  = (row >> 1) & 3;
            #pragma unroll
            for (int ks = 0; ks < 2; ks++)
                off_a[mi][ks] = (uint32_t)(row * 64 + (((ks * 2 + hi_a) ^ sw) << 4));
        }
        const int hi_b = (lane >> 3) & 1;        // B chunk-high selector
        #pragma unroll
        for (int g = 0; g < 2; g++) {
            const int row = warp_n + g * 16 + (lane & 7) + (lane >> 4) * 8;
            const int sw  = (row >> 1) & 3;
            #pragma unroll
            for (int ks = 0; ks < 2; ks++)
                off_b[g][ks] = (uint32_t)(TILE_B + row * 64 + (((ks * 2 + hi_b) ^ sw) << 4));
        }
    }

    float c[4][4][4];
    #pragma unroll
    for (int mi = 0; mi < 4; mi++)
        #pragma unroll
        for (int ni = 0; ni < 4; ni++)
            #pragma unroll
            for (int r = 0; r < 4; r++) c[mi][ni][r] = 0.f;

    // pipeline prologue
    if (tid == 0) {
        #pragma unroll
        for (int s = 0; s < 4; s++)
            MBARRIER_INIT(sbase + SMEM_MBAR + s * 8, 1);
    }
    __syncthreads();
    if (tid == 0) {
        #pragma unroll
        for (int p = 0; p < 3; p++) {
            const uint32_t mbar = sbase + SMEM_MBAR + p * 8;
            MBARRIER_EXPECT_TX(mbar, STAGE_B);
            bulk_g2s(sbase + p * STAGE_B,          Ax + (size_t)p * TILE_B, TILE_B, mbar);
            bulk_g2s(sbase + p * STAGE_B + TILE_B, Bw + (size_t)p * TILE_B, TILE_B, mbar);
        }
    }

    for (int kt = 0; kt < 32; kt++) {
        __syncthreads();   // all warps done with kt-1 -> stage (kt+3)&3 free
        if (tid == 0 && kt + 3 < 32) {
            const int p = kt + 3, s = p & 3;
            const uint32_t mbar = sbase + SMEM_MBAR + s * 8;
            MBARRIER_EXPECT_TX(mbar, STAGE_B);
            bulk_g2s(sbase + s * STAGE_B,          Ax + (size_t)p * TILE_B, TILE_B, mbar);
            bulk_g2s(sbase + s * STAGE_B + TILE_B, Bw + (size_t)p * TILE_B, TILE_B, mbar);
        }
        MBARRIER_WAIT_PARITY(sbase + SMEM_MBAR + (kt & 3) * 8, (kt >> 2) & 1);

        const uint32_t stage = sbase + (uint32_t)(kt & 3) * STAGE_B;
        #pragma unroll
        for (int ks = 0; ks < 2; ks++) {
            uint32_t a[4][4];
            #pragma unroll
            for (int mi = 0; mi < 4; mi++)
                ldsm_x4(a[mi], stage + off_a[mi][ks]);
            uint32_t b[4][2];
            {
                uint32_t r[4];
                ldsm_x4(r, stage + off_b[0][ks]);               // n 0..15
                b[0][0] = r[0]; b[0][1] = r[1]; b[1][0] = r[2]; b[1][1] = r[3];
                ldsm_x4(r, stage + off_b[1][ks]);               // n 16..31
                b[2][0] = r[0]; b[2][1] = r[1]; b[3][0] = r[2]; b[3][1] = r[3];
            }
            #pragma unroll
            for (int mi = 0; mi < 4; mi++)
                #pragma unroll
                for (int ni = 0; ni < 4; ni++)
                    mma_f16(c[mi][ni], a[mi], b[ni]);
        }
    }

    // epilogue: bias + relu -> fp16 stores
    #pragma unroll
    for (int mi = 0; mi < 4; mi++) {
        #pragma unroll
        for (int ni = 0; ni < 4; ni++) {
            const int rbase = m0 + warp_m + mi * 16 + gid;
            const int col   = warp_n + ni * 8 + 2 * tig;
            const float b0 = biassm[col], b1 = biassm[col + 1];
            __half2 p0 = __floats2half2_rn(fmaxf(c[mi][ni][0] + b0, 0.f),
                                           fmaxf(c[mi][ni][1] + b1, 0.f));
            __half2 p1 = __floats2half2_rn(fmaxf(c[mi][ni][2] + b0, 0.f),
                                           fmaxf(c[mi][ni][3] + b1, 0.f));
            *(__half2*)(Y + (size_t)rbase * HD + n0 + col)       = p0;
            *(__half2*)(Y + (size_t)(rbase + 8) * HD + n0 + col) = p1;
        }
    }
}

// ---------------------------------------------------------------------------
// K3: gated mixture — all 3 tasks per thread
// ---------------------------------------------------------------------------
__global__ __launch_bounds__(256) void mix_kernel(float* __restrict__ out)
{
    const size_t idx = (size_t)blockIdx.x * blockDim.x + threadIdx.x;
    const int h4 = (int)(idx & 255);
    const int b  = (int)(idx >> 8);

    float g[NTASK][8];
    #pragma unroll
    for (int t = 0; t < NTASK; t++) {
        const float4* gp = (const float4*)(g_gates + ((size_t)t * BATCH + b) * 8);
        float4 g0 = gp[0], g1 = gp[1];
        g[t][0] = g0.x; g[t][1] = g0.y; g[t][2] = g0.z; g[t][3] = g0.w;
        g[t][4] = g1.x; g[t][5] = g1.y; g[t][6] = g1.z; g[t][7] = g1.w;
    }

    float4 acc[NTASK];
    #pragma unroll
    for (int t = 0; t < NTASK; t++) acc[t] = make_float4(0.f, 0.f, 0.f, 0.f);

    #pragma unroll
    for (int j = 0; j < 4; j++) {    // shared experts -> all tasks (slot 4+j)
        const uint2 v = *(const uint2*)(g_yh + ((size_t)j * BATCH + b) * HD + (size_t)h4 * 4);
        const float2 f01 = __half22float2(*(const __half2*)&v.x);
        const float2 f23 = __half22float2(*(const __half2*)&v.y);
        #pragma unroll
        for (int t = 0; t < NTASK; t++) {
            const float gv = g[t][4 + j];
            acc[t].x = fmaf(gv, f01.x, acc[t].x);
            acc[t].y = fmaf(gv, f01.y, acc[t].y);
            acc[t].z = fmaf(gv, f23.x, acc[t].z);
            acc[t].w = fmaf(gv, f23.y, acc[t].w);
        }
    }
    #pragma unroll
    for (int t = 0; t < NTASK; t++) {   // task-specific experts (slot j)
        #pragma unroll
        for (int j = 0; j < 4; j++) {
            const int ei = 4 + t * 4 + j;
            const uint2 v = *(const uint2*)(g_yh + ((size_t)ei * BATCH + b) * HD + (size_t)h4 * 4);
            const float2 f01 = __half22float2(*(const __half2*)&v.x);
            const float2 f23 = __half22float2(*(const __half2*)&v.y);
            const float gv = g[t][j];
            acc[t].x = fmaf(gv, f01.x, acc[t].x);
            acc[t].y = fmaf(gv, f01.y, acc[t].y);
            acc[t].z = fmaf(gv, f23.x, acc[t].z);
            acc[t].w = fmaf(gv, f23.y, acc[t].w);
        }
    }

    #pragma unroll
    for (int t = 0; t < NTASK; t++)
        *(float4*)(out + ((size_t)t * BATCH + b) * HD + (size_t)h4 * 4) = acc[t];
}

// ---------------------------------------------------------------------------
extern "C" void kernel_launch(void* const* d_in, const int* in_sizes, int n_in,
                              void* d_out, int out_size)
{
    (void)in_sizes; (void)n_in; (void)out_size;
    const float* x  = (const float*)d_in[0];
    const float* Ws = (const float*)d_in[1];
    const float* bs = (const float*)d_in[2];
    const float* Wt = (const float*)d_in[3];
    const float* bt = (const float*)d_in[4];
    const float* Wg = (const float*)d_in[5];
    float* out = (float*)d_out;

    cudaFuncSetAttribute(expert_gemm_f16,
                         cudaFuncAttributeMaxDynamicSharedMemorySize, SMEM_GEMM);
    cudaFuncSetAttribute(gate_kernel,
                         cudaFuncAttributeMaxDynamicSharedMemorySize, GATE_SMEM);

    pack_x<<<4096, 256>>>(x);
    pack_w<<<dim3(32, 32, 16), 256>>>(Ws, Wt);
    gate_kernel<<<BATCH / GATE_ROWS, 256, GATE_SMEM>>>(x, Wg);
    expert_gemm_f16<<<dim3(8, 64, 16), 256, SMEM_GEMM>>>(bs, bt);

    const size_t nthreads = (size_t)BATCH * (HD / 4);
    mix_kernel<<<(unsigned)(nthreads / 256), 256>>>(out);
}

// round 13
// speedup vs baseline: 1.5909x; 1.0290x over previous
#include <cuda_runtime.h>
#include <cuda_fp16.h>
#include <cstdint>

// CGC layer — fp16 mma.sync (f32 acc) + cp.async.bulk; K=64 stages (16 KB per
// operand), 3-stage mbarrier pipeline, 128x128 CTA tile, 2 CTAs/SM.
// Inputs: x(8192,1024) Ws(4,1024,1024) bs(4,1024) Wt(3,4,1024,1024) bt(3,4,1024) Wg(3,1024,8)
// Output: mixture (3, 8192, 1024) f32

#define BATCH 8192
#define DM    1024
#define HD    1024
#define NTASK 3

// packed 8KB sub-tile: 128 rows x 32 k fp16; row r: chunk c at r*64 + ((c ^ ((r>>1)&3))*16)
#define TILE_B 8192

__device__ __half g_yh[16ull * BATCH * HD];                 // 256 MB expert outputs
__device__ float  g_gates[NTASK * BATCH * 8];
__device__ __align__(128) unsigned char g_xp[64ull * 32 * TILE_B];       // 16 MB packed x
__device__ __align__(128) unsigned char g_wp[16ull * 8 * 32 * TILE_B];   // 32 MB packed W^T

// ---------------------------------------------------------------------------
// helpers
// ---------------------------------------------------------------------------
__device__ __forceinline__ uint32_t smem_u32(const void* p) {
    uint32_t a;
    asm("{ .reg .u64 t; cvta.to.shared.u64 t, %1; cvt.u32.u64 %0, t; }" : "=r"(a) : "l"(p));
    return a;
}
__device__ __forceinline__ void mma_f16(float* c, const uint32_t* a, const uint32_t* b) {
    asm volatile(
        "mma.sync.aligned.m16n8k16.row.col.f32.f16.f16.f32 "
        "{%0,%1,%2,%3}, {%4,%5,%6,%7}, {%8,%9}, {%0,%1,%2,%3};"
        : "+f"(c[0]), "+f"(c[1]), "+f"(c[2]), "+f"(c[3])
        : "r"(a[0]), "r"(a[1]), "r"(a[2]), "r"(a[3]), "r"(b[0]), "r"(b[1]));
}
__device__ __forceinline__ void ldsm_x4(uint32_t* r, uint32_t addr) {
    asm volatile("ldmatrix.sync.aligned.m8n8.x4.shared.b16 {%0,%1,%2,%3}, [%4];"
        : "=r"(r[0]), "=r"(r[1]), "=r"(r[2]), "=r"(r[3]) : "r"(addr));
}
__device__ __forceinline__ void bulk_g2s(uint32_t dst, const void* src,
                                         uint32_t bytes, uint32_t mbar) {
    asm volatile(
        "cp.async.bulk.shared::cluster.global.mbarrier::complete_tx::bytes "
        "[%0], [%1], %2, [%3];"
        :: "r"(dst), "l"(src), "r"(bytes), "r"(mbar) : "memory");
}
#define MBARRIER_INIT(mbar, count) \
    asm volatile("mbarrier.init.shared.b64 [%0], %1;" \
                 :: "r"((uint32_t)(mbar)), "r"((uint32_t)(count)) : "memory")
#define MBARRIER_EXPECT_TX(mbar, tx) \
    asm volatile("mbarrier.arrive.expect_tx.shared.b64 _, [%0], %1;" \
                 :: "r"((uint32_t)(mbar)), "r"((uint32_t)(tx)) : "memory")
#define MBARRIER_WAIT_PARITY(mbar, par) do { \
    uint32_t _m = (uint32_t)(mbar), _p = (uint32_t)(par), _d; \
    asm volatile( \
        "{\n\t.reg .pred p;\n\t" \
        "mbarrier.try_wait.parity.acquire.cta.shared::cta.b64 p, [%1], %2;\n\t" \
        "selp.b32 %0, 1, 0, p;\n\t}" \
        : "=r"(_d) : "r"(_m), "r"(_p) : "memory"); \
    if (!_d) { \
        asm volatile( \
            "{\n\t.reg .pred P1;\n\t" \
            "WL_%=:\n\t" \
            "mbarrier.try_wait.parity.acquire.cta.shared::cta.b64 P1, [%0], %1, 0x989680;\n\t" \
            "@P1 bra.uni WD_%=;\n\t" \
            "bra.uni WL_%=;\n\t" \
            "WD_%=:\n\t}" \
            :: "r"(_m), "r"(_p) : "memory"); \
    } \
} while (0)

// ---------------------------------------------------------------------------
// K0a: pack x -> g_xp  (fp32 -> fp16, tiled + swizzled)
// ---------------------------------------------------------------------------
__global__ __launch_bounds__(256) void pack_x(const float* __restrict__ x)
{
    const uint32_t idx = blockIdx.x * 256 + threadIdx.x;   // 1,048,576 chunks
    const uint32_t mb = idx >> 14;
    const uint32_t rem = idx & 16383;
    const uint32_t kt = rem >> 9;
    const uint32_t t  = rem & 511;
    const uint32_t r  = t >> 2, c = t & 3;

    const float* src = x + ((size_t)mb * 128 + r) * DM + kt * 32 + c * 8;
    float4 v0 = *(const float4*)src;
    float4 v1 = *(const float4*)(src + 4);
    __half2 h[4];
    h[0] = __floats2half2_rn(v0.x, v0.y);
    h[1] = __floats2half2_rn(v0.z, v0.w);
    h[2] = __floats2half2_rn(v1.x, v1.y);
    h[3] = __floats2half2_rn(v1.z, v1.w);

    unsigned char* dst = g_xp + ((size_t)mb * 32 + kt) * TILE_B
                       + r * 64 + ((c ^ ((r >> 1) & 3)) << 4);
    *(uint4*)dst = *(uint4*)h;
}

// ---------------------------------------------------------------------------
// K0b: pack W -> g_wp  (fp32 [e][k][n] -> fp16 [e][nb][kt] tiles, swizzled)
// ---------------------------------------------------------------------------
__global__ __launch_bounds__(256) void pack_w(const float* __restrict__ Ws,
                                              const float* __restrict__ Wt)
{
    __shared__ float t[32][33];
    const int e  = blockIdx.z;
    const float* src = (e < 4) ? Ws + (size_t)e * DM * HD
                               : Wt + (size_t)(e - 4) * DM * HD;
    const int n0 = blockIdx.x * 32;
    const int k0 = blockIdx.y * 32;
    const int tx = threadIdx.x & 31;
    const int ty = threadIdx.x >> 5;

    #pragma unroll
    for (int i = 0; i < 32; i += 8)
        t[ty + i][tx] = src[(size_t)(k0 + ty + i) * HD + n0 + tx];   // t[k][n]
    __syncthreads();

    if (threadIdx.x < 128) {
        const int rl = threadIdx.x >> 2;     // 0..31 local n-row
        const int c  = threadIdx.x & 3;      // chunk
        const int rr = (n0 & 127) + rl;      // row within 128-row tile
        const int nb = n0 >> 7;
        const int kt = k0 >> 5;

        __half2 h[4];
        #pragma unroll
        for (int j = 0; j < 4; j++)
            h[j] = __floats2half2_rn(t[c * 8 + j * 2][rl], t[c * 8 + j * 2 + 1][rl]);

        unsigned char* dst = g_wp + (((size_t)e * 8 + nb) * 32 + kt) * TILE_B
                           + rr * 64 + ((c ^ ((rr >> 1) & 3)) << 4);
        *(uint4*)dst = *(uint4*)h;
    }
}

// ---------------------------------------------------------------------------
// K1: gate logits + softmax (Wg staged in smem)
// ---------------------------------------------------------------------------
#define GATE_ROWS 32
#define GATE_SMEM (NTASK * DM * 8 * 4)

__global__ __launch_bounds__(256) void gate_kernel(const float* __restrict__ x,
                                                   const float* __restrict__ Wg)
{
    extern __shared__ float wgs[];
    const int tid = threadIdx.x;

    for (int i = tid; i < NTASK * DM * 8 / 4; i += 256)
        ((float4*)wgs)[i] = ((const float4*)Wg)[i];
    __syncthreads();

    const int w    = tid >> 5;
    const int lane = tid & 31;
    const int b0   = blockIdx.x * GATE_ROWS;

    for (int i = w; i < GATE_ROWS * NTASK; i += 8) {
        const int row = i & 31;
        const int t   = i >> 5;
        const float* xr = x + (size_t)(b0 + row) * DM;
        const float* wt = wgs + (size_t)t * DM * 8;

        float acc[8] = {0.f, 0.f, 0.f, 0.f, 0.f, 0.f, 0.f, 0.f};
        for (int d = lane; d < DM; d += 32) {
            const float xv = xr[d];
            float4 w0 = *(const float4*)(wt + (size_t)d * 8);
            float4 w1 = *(const float4*)(wt + (size_t)d * 8 + 4);
            acc[0] = fmaf(xv, w0.x, acc[0]);
            acc[1] = fmaf(xv, w0.y, acc[1]);
            acc[2] = fmaf(xv, w0.z, acc[2]);
            acc[3] = fmaf(xv, w0.w, acc[3]);
            acc[4] = fmaf(xv, w1.x, acc[4]);
            acc[5] = fmaf(xv, w1.y, acc[5]);
            acc[6] = fmaf(xv, w1.z, acc[6]);
            acc[7] = fmaf(xv, w1.w, acc[7]);
        }
        #pragma unroll
        for (int off = 16; off > 0; off >>= 1) {
            #pragma unroll
            for (int j = 0; j < 8; j++)
                acc[j] += __shfl_down_sync(0xffffffffu, acc[j], off);
        }
        if (lane == 0) {
            float m = acc[0];
            #pragma unroll
            for (int j = 1; j < 8; j++) m = fmaxf(m, acc[j]);
            float e[8], s = 0.f;
            #pragma unroll
            for (int j = 0; j < 8; j++) { e[j] = expf(acc[j] - m); s += e[j]; }
            float inv = 1.f / s;
            float* gp = g_gates + ((size_t)t * BATCH + (b0 + row)) * 8;
            #pragma unroll
            for (int j = 0; j < 8; j++) gp[j] = e[j] * inv;
        }
    }
}

// ---------------------------------------------------------------------------
// K2: expert GEMM. 128x128 CTA tile, K=64 stages, 3-stage bulk pipeline,
// 8 warps (2m x 4n), 64x32 warp tiles, 2 CTAs/SM.
// SMEM per stage: A 16KB (k 0..63) + B 16KB = 32KB; 3 stages = 96KB.
// ---------------------------------------------------------------------------
#define STAGE_B   32768
#define SMEM_MBAR (3 * STAGE_B)            // 98304
#define SMEM_BIAS (SMEM_MBAR + 64)         // 98368
#define SMEM_GEMM (SMEM_BIAS + 512)        // 98880

__global__ __launch_bounds__(256, 2) void expert_gemm_f16(const float* __restrict__ bs,
                                                          const float* __restrict__ bt)
{
    extern __shared__ char smem[];
    const uint32_t sbase = smem_u32(smem);
    float* biassm = (float*)(smem + SMEM_BIAS);

    const int tid  = threadIdx.x;
    const int w    = tid >> 5;
    const int lane = tid & 31;
    const int gid  = lane >> 2;
    const int tig  = lane & 3;
    const int warp_m = (w >> 2) * 64;   // 0,64
    const int warp_n = (w & 3) * 32;    // 0,32,64,96

    const int e  = blockIdx.z;
    const int nb = blockIdx.x;          // 0..7
    const int mb = blockIdx.y;          // 0..63
    const int n0 = nb * 128;
    const int m0 = mb * 128;

    const unsigned char* Ax = g_xp + (size_t)mb * 32 * TILE_B;
    const unsigned char* Bw = g_wp + ((size_t)e * 8 + nb) * 32 * TILE_B;
    const float* bias = (e < 4) ? bs + (size_t)e * HD : bt + (size_t)(e - 4) * HD;
    __half* Y = g_yh + (size_t)e * BATCH * HD;

    if (tid < 128) biassm[tid] = bias[n0 + tid];

    // swizzled ldsm lane offsets within a stage; ks&1 selects chunk-pair,
    // ks>>1 selects the 8KB sub-tile (+8192).
    uint32_t off_a[4][2], off_b[2][2];
    {
        const int hi_a = lane >> 4;
        #pragma unroll
        for (int mi = 0; mi < 4; mi++) {
            const int row = warp_m + mi * 16 + (lane & 7) + ((lane >> 3) & 1) * 8;
            const int sw  = (row >> 1) & 3;
            #pragma unroll
            for (int ks = 0; ks < 2; ks++)
                off_a[mi][ks] = (uint32_t)(row * 64 + (((ks * 2 + hi_a) ^ sw) << 4));
        }
        const int hi_b = (lane >> 3) & 1;
        #pragma unroll
        for (int g = 0; g < 2; g++) {
            const int row = warp_n + g * 16 + (lane & 7) + (lane >> 4) * 8;
            const int sw  = (row >> 1) & 3;
            #pragma unroll
            for (int ks = 0; ks < 2; ks++)
                off_b[g][ks] = (uint32_t)(2 * TILE_B + row * 64
                                          + (((ks * 2 + hi_b) ^ sw) << 4));
        }
    }

    float c[4][4][4];
    #pragma unroll
    for (int mi = 0; mi < 4; mi++)
        #pragma unroll
        for (int ni = 0; ni < 4; ni++)
            #pragma unroll
            for (int r = 0; r < 4; r++) c[mi][ni][r] = 0.f;

    // pipeline prologue: init mbarriers, preload stages 0,1 (p = K64-tile idx)
    if (tid == 0) {
        #pragma unroll
        for (int s = 0; s < 3; s++)
            MBARRIER_INIT(sbase + SMEM_MBAR + s * 8, 1);
    }
    __syncthreads();
    if (tid == 0) {
        #pragma unroll
        for (int p = 0; p < 2; p++) {
            const uint32_t mbar = sbase + SMEM_MBAR + p * 8;
            MBARRIER_EXPECT_TX(mbar, STAGE_B);
            bulk_g2s(sbase + p * STAGE_B,              Ax + (size_t)p * 2 * TILE_B,
                     2 * TILE_B, mbar);
            bulk_g2s(sbase + p * STAGE_B + 2 * TILE_B, Bw + (size_t)p * 2 * TILE_B,
                     2 * TILE_B, mbar);
        }
    }

    int cs = 0, cph = 0;      // compute cursor (stage, parity)
    int ls = 2;               // load-target stage for tile kt+2

    for (int kt = 0; kt < 16; kt++) {
        __syncthreads();      // all warps done with kt-1 -> stage ls free
        if (tid == 0 && kt + 2 < 16) {
            const int p = kt + 2;
            const uint32_t mbar = sbase + SMEM_MBAR + ls * 8;
            MBARRIER_EXPECT_TX(mbar, STAGE_B);
            bulk_g2s(sbase + ls * STAGE_B,              Ax + (size_t)p * 2 * TILE_B,
                     2 * TILE_B, mbar);
            bulk_g2s(sbase + ls * STAGE_B + 2 * TILE_B, Bw + (size_t)p * 2 * TILE_B,
                     2 * TILE_B, mbar);
        }
        MBARRIER_WAIT_PARITY(sbase + SMEM_MBAR + cs * 8, cph);

        const uint32_t stage = sbase + (uint32_t)cs * STAGE_B;
        #pragma unroll
        for (int ks = 0; ks < 4; ks++) {
            const uint32_t sub = (uint32_t)((ks >> 1) * TILE_B);
            uint32_t a[4][4];
            #pragma unroll
            for (int mi = 0; mi < 4; mi++)
                ldsm_x4(a[mi], stage + sub + off_a[mi][ks & 1]);
            uint32_t b[4][2];
            {
                uint32_t r[4];
                ldsm_x4(r, stage + sub + off_b[0][ks & 1]);    // n 0..15
                b[0][0] = r[0]; b[0][1] = r[1]; b[1][0] = r[2]; b[1][1] = r[3];
                ldsm_x4(r, stage + sub + off_b[1][ks & 1]);    // n 16..31
                b[2][0] = r[0]; b[2][1] = r[1]; b[3][0] = r[2]; b[3][1] = r[3];
            }
            #pragma unroll
            for (int mi = 0; mi < 4; mi++)
                #pragma unroll
                for (int ni = 0; ni < 4; ni++)
                    mma_f16(c[mi][ni], a[mi], b[ni]);
        }

        if (++cs == 3) { cs = 0; cph ^= 1; }
        if (++ls == 3) { ls = 0; }
    }

    // epilogue: bias + relu -> fp16 stores
    #pragma unroll
    for (int mi = 0; mi < 4; mi++) {
        #pragma unroll
        for (int ni = 0; ni < 4; ni++) {
            const int rbase = m0 + warp_m + mi * 16 + gid;
            const int col   = warp_n + ni * 8 + 2 * tig;
            const float b0 = biassm[col], b1 = biassm[col + 1];
            __half2 p0 = __floats2half2_rn(fmaxf(c[mi][ni][0] + b0, 0.f),
                                           fmaxf(c[mi][ni][1] + b1, 0.f));
            __half2 p1 = __floats2half2_rn(fmaxf(c[mi][ni][2] + b0, 0.f),
                                           fmaxf(c[mi][ni][3] + b1, 0.f));
            *(__half2*)(Y + (size_t)rbase * HD + n0 + col)       = p0;
            *(__half2*)(Y + (size_t)(rbase + 8) * HD + n0 + col) = p1;
        }
    }
}

// ---------------------------------------------------------------------------
// K3: gated mixture — all 3 tasks per thread
// ---------------------------------------------------------------------------
__global__ __launch_bounds__(256) void mix_kernel(float* __restrict__ out)
{
    const size_t idx = (size_t)blockIdx.x * blockDim.x + threadIdx.x;
    const int h4 = (int)(idx & 255);
    const int b  = (int)(idx >> 8);

    float g[NTASK][8];
    #pragma unroll
    for (int t = 0; t < NTASK; t++) {
        const float4* gp = (const float4*)(g_gates + ((size_t)t * BATCH + b) * 8);
        float4 g0 = gp[0], g1 = gp[1];
        g[t][0] = g0.x; g[t][1] = g0.y; g[t][2] = g0.z; g[t][3] = g0.w;
        g[t][4] = g1.x; g[t][5] = g1.y; g[t][6] = g1.z; g[t][7] = g1.w;
    }

    float4 acc[NTASK];
    #pragma unroll
    for (int t = 0; t < NTASK; t++) acc[t] = make_float4(0.f, 0.f, 0.f, 0.f);

    #pragma unroll
    for (int j = 0; j < 4; j++) {    // shared experts -> all tasks (slot 4+j)
        const uint2 v = *(const uint2*)(g_yh + ((size_t)j * BATCH + b) * HD + (size_t)h4 * 4);
        const float2 f01 = __half22float2(*(const __half2*)&v.x);
        const float2 f23 = __half22float2(*(const __half2*)&v.y);
        #pragma unroll
        for (int t = 0; t < NTASK; t++) {
            const float gv = g[t][4 + j];
            acc[t].x = fmaf(gv, f01.x, acc[t].x);
            acc[t].y = fmaf(gv, f01.y, acc[t].y);
            acc[t].z = fmaf(gv, f23.x, acc[t].z);
            acc[t].w = fmaf(gv, f23.y, acc[t].w);
        }
    }
    #pragma unroll
    for (int t = 0; t < NTASK; t++) {   // task-specific experts (slot j)
        #pragma unroll
        for (int j = 0; j < 4; j++) {
            const int ei = 4 + t * 4 + j;
            const uint2 v = *(const uint2*)(g_yh + ((size_t)ei * BATCH + b) * HD + (size_t)h4 * 4);
            const float2 f01 = __half22float2(*(const __half2*)&v.x);
            const float2 f23 = __half22float2(*(const __half2*)&v.y);
            const float gv = g[t][j];
            acc[t].x = fmaf(gv, f01.x, acc[t].x);
            acc[t].y = fmaf(gv, f01.y, acc[t].y);
            acc[t].z = fmaf(gv, f23.x, acc[t].z);
            acc[t].w = fmaf(gv, f23.y, acc[t].w);
        }
    }

    #pragma unroll
    for (int t = 0; t < NTASK; t++)
        *(float4*)(out + ((size_t)t * BATCH + b) * HD + (size_t)h4 * 4) = acc[t];
}

// ---------------------------------------------------------------------------
extern "C" void kernel_launch(void* const* d_in, const int* in_sizes, int n_in,
                              void* d_out, int out_size)
{
    (void)in_sizes; (void)n_in; (void)out_size;
    const float* x  = (const float*)d_in[0];
    const float* Ws = (const float*)d_in[1];
    const float* bs = (const float*)d_in[2];
    const float* Wt = (const float*)d_in[3];
    const float* bt = (const float*)d_in[4];
    const float* Wg = (const float*)d_in[5];
    float* out = (float*)d_out;

    cudaFuncSetAttribute(expert_gemm_f16,
                         cudaFuncAttributeMaxDynamicSharedMemorySize, SMEM_GEMM);
    cudaFuncSetAttribute(gate_kernel,
                         cudaFuncAttributeMaxDynamicSharedMemorySize, GATE_SMEM);

    pack_x<<<4096, 256>>>(x);
    pack_w<<<dim3(32, 32, 16), 256>>>(Ws, Wt);
    gate_kernel<<<BATCH / GATE_ROWS, 256, GATE_SMEM>>>(x, Wg);
    expert_gemm_f16<<<dim3(8, 64, 16), 256, SMEM_GEMM>>>(bs, bt);

    const size_t nthreads = (size_t)BATCH * (HD / 4);
    mix_kernel<<<(unsigned)(nthreads / 256), 256>>>(out);
}

// round 14
// speedup vs baseline: 1.6821x; 1.0573x over previous
#include <cuda_runtime.h>
#include <cuda_fp16.h>
#include <cstdint>

// CGC layer — fp16 mma.sync (f32 acc) + cp.async.bulk; K=64 stages, 3-stage
// pipeline with full/empty mbarriers (NO in-loop __syncthreads — free warp
// skew), 128x128 CTA tile, 2 CTAs/SM.
// Inputs: x(8192,1024) Ws(4,1024,1024) bs(4,1024) Wt(3,4,1024,1024) bt(3,4,1024) Wg(3,1024,8)
// Output: mixture (3, 8192, 1024) f32

#define BATCH 8192
#define DM    1024
#define HD    1024
#define NTASK 3

// packed 8KB sub-tile: 128 rows x 32 k fp16; row r: chunk c at r*64 + ((c ^ ((r>>1)&3))*16)
#define TILE_B 8192

__device__ __half g_yh[16ull * BATCH * HD];                 // 256 MB expert outputs
__device__ float  g_gates[NTASK * BATCH * 8];
__device__ __align__(128) unsigned char g_xp[64ull * 32 * TILE_B];       // 16 MB packed x
__device__ __align__(128) unsigned char g_wp[16ull * 8 * 32 * TILE_B];   // 32 MB packed W^T

// ---------------------------------------------------------------------------
// helpers
// ---------------------------------------------------------------------------
__device__ __forceinline__ uint32_t smem_u32(const void* p) {
    uint32_t a;
    asm("{ .reg .u64 t; cvta.to.shared.u64 t, %1; cvt.u32.u64 %0, t; }" : "=r"(a) : "l"(p));
    return a;
}
__device__ __forceinline__ void mma_f16(float* c, const uint32_t* a, const uint32_t* b) {
    asm volatile(
        "mma.sync.aligned.m16n8k16.row.col.f32.f16.f16.f32 "
        "{%0,%1,%2,%3}, {%4,%5,%6,%7}, {%8,%9}, {%0,%1,%2,%3};"
        : "+f"(c[0]), "+f"(c[1]), "+f"(c[2]), "+f"(c[3])
        : "r"(a[0]), "r"(a[1]), "r"(a[2]), "r"(a[3]), "r"(b[0]), "r"(b[1]));
}
__device__ __forceinline__ void ldsm_x4(uint32_t* r, uint32_t addr) {
    asm volatile("ldmatrix.sync.aligned.m8n8.x4.shared.b16 {%0,%1,%2,%3}, [%4];"
        : "=r"(r[0]), "=r"(r[1]), "=r"(r[2]), "=r"(r[3]) : "r"(addr));
}
__device__ __forceinline__ void bulk_g2s(uint32_t dst, const void* src,
                                         uint32_t bytes, uint32_t mbar) {
    asm volatile(
        "cp.async.bulk.shared::cluster.global.mbarrier::complete_tx::bytes "
        "[%0], [%1], %2, [%3];"
        :: "r"(dst), "l"(src), "r"(bytes), "r"(mbar) : "memory");
}
#define MBARRIER_INIT(mbar, count) \
    asm volatile("mbarrier.init.shared.b64 [%0], %1;" \
                 :: "r"((uint32_t)(mbar)), "r"((uint32_t)(count)) : "memory")
#define MBARRIER_EXPECT_TX(mbar, tx) \
    asm volatile("mbarrier.arrive.expect_tx.shared.b64 _, [%0], %1;" \
                 :: "r"((uint32_t)(mbar)), "r"((uint32_t)(tx)) : "memory")
#define MBARRIER_ARRIVE(mbar) \
    asm volatile("mbarrier.arrive.shared.b64 _, [%0];" \
                 :: "r"((uint32_t)(mbar)) : "memory")
#define MBARRIER_WAIT_PARITY(mbar, par) do { \
    uint32_t _m = (uint32_t)(mbar), _p = (uint32_t)(par), _d; \
    asm volatile( \
        "{\n\t.reg .pred p;\n\t" \
        "mbarrier.try_wait.parity.acquire.cta.shared::cta.b64 p, [%1], %2;\n\t" \
        "selp.b32 %0, 1, 0, p;\n\t}" \
        : "=r"(_d) : "r"(_m), "r"(_p) : "memory"); \
    if (!_d) { \
        asm volatile( \
            "{\n\t.reg .pred P1;\n\t" \
            "WL_%=:\n\t" \
            "mbarrier.try_wait.parity.acquire.cta.shared::cta.b64 P1, [%0], %1, 0x989680;\n\t" \
            "@P1 bra.uni WD_%=;\n\t" \
            "bra.uni WL_%=;\n\t" \
            "WD_%=:\n\t}" \
            :: "r"(_m), "r"(_p) : "memory"); \
    } \
} while (0)

// ---------------------------------------------------------------------------
// K0a: pack x -> g_xp  (fp32 -> fp16, tiled + swizzled)
// ---------------------------------------------------------------------------
__global__ __launch_bounds__(256) void pack_x(const float* __restrict__ x)
{
    const uint32_t idx = blockIdx.x * 256 + threadIdx.x;
    const uint32_t mb = idx >> 14;
    const uint32_t rem = idx & 16383;
    const uint32_t kt = rem >> 9;
    const uint32_t t  = rem & 511;
    const uint32_t r  = t >> 2, c = t & 3;

    const float* src = x + ((size_t)mb * 128 + r) * DM + kt * 32 + c * 8;
    float4 v0 = *(const float4*)src;
    float4 v1 = *(const float4*)(src + 4);
    __half2 h[4];
    h[0] = __floats2half2_rn(v0.x, v0.y);
    h[1] = __floats2half2_rn(v0.z, v0.w);
    h[2] = __floats2half2_rn(v1.x, v1.y);
    h[3] = __floats2half2_rn(v1.z, v1.w);

    unsigned char* dst = g_xp + ((size_t)mb * 32 + kt) * TILE_B
                       + r * 64 + ((c ^ ((r >> 1) & 3)) << 4);
    *(uint4*)dst = *(uint4*)h;
}

// ---------------------------------------------------------------------------
// K0b: pack W -> g_wp  (fp32 [e][k][n] -> fp16 [e][nb][kt] tiles, swizzled)
// ---------------------------------------------------------------------------
__global__ __launch_bounds__(256) void pack_w(const float* __restrict__ Ws,
                                              const float* __restrict__ Wt)
{
    __shared__ float t[32][33];
    const int e  = blockIdx.z;
    const float* src = (e < 4) ? Ws + (size_t)e * DM * HD
                               : Wt + (size_t)(e - 4) * DM * HD;
    const int n0 = blockIdx.x * 32;
    const int k0 = blockIdx.y * 32;
    const int tx = threadIdx.x & 31;
    const int ty = threadIdx.x >> 5;

    #pragma unroll
    for (int i = 0; i < 32; i += 8)
        t[ty + i][tx] = src[(size_t)(k0 + ty + i) * HD + n0 + tx];   // t[k][n]
    __syncthreads();

    if (threadIdx.x < 128) {
        const int rl = threadIdx.x >> 2;
        const int c  = threadIdx.x & 3;
        const int rr = (n0 & 127) + rl;
        const int nb = n0 >> 7;
        const int kt = k0 >> 5;

        __half2 h[4];
        #pragma unroll
        for (int j = 0; j < 4; j++)
            h[j] = __floats2half2_rn(t[c * 8 + j * 2][rl], t[c * 8 + j * 2 + 1][rl]);

        unsigned char* dst = g_wp + (((size_t)e * 8 + nb) * 32 + kt) * TILE_B
                           + rr * 64 + ((c ^ ((rr >> 1) & 3)) << 4);
        *(uint4*)dst = *(uint4*)h;
    }
}

// ---------------------------------------------------------------------------
// K1: gate logits + softmax (Wg staged in smem)
// ---------------------------------------------------------------------------
#define GATE_ROWS 32
#define GATE_SMEM (NTASK * DM * 8 * 4)

__global__ __launch_bounds__(256) void gate_kernel(const float* __restrict__ x,
                                                   const float* __restrict__ Wg)
{
    extern __shared__ float wgs[];
    const int tid = threadIdx.x;

    for (int i = tid; i < NTASK * DM * 8 / 4; i += 256)
        ((float4*)wgs)[i] = ((const float4*)Wg)[i];
    __syncthreads();

    const int w    = tid >> 5;
    const int lane = tid & 31;
    const int b0   = blockIdx.x * GATE_ROWS;

    for (int i = w; i < GATE_ROWS * NTASK; i += 8) {
        const int row = i & 31;
        const int t   = i >> 5;
        const float* xr = x + (size_t)(b0 + row) * DM;
        const float* wt = wgs + (size_t)t * DM * 8;

        float acc[8] = {0.f, 0.f, 0.f, 0.f, 0.f, 0.f, 0.f, 0.f};
        for (int d = lane; d < DM; d += 32) {
            const float xv = xr[d];
            float4 w0 = *(const float4*)(wt + (size_t)d * 8);
            float4 w1 = *(const float4*)(wt + (size_t)d * 8 + 4);
            acc[0] = fmaf(xv, w0.x, acc[0]);
            acc[1] = fmaf(xv, w0.y, acc[1]);
            acc[2] = fmaf(xv, w0.z, acc[2]);
            acc[3] = fmaf(xv, w0.w, acc[3]);
            acc[4] = fmaf(xv, w1.x, acc[4]);
            acc[5] = fmaf(xv, w1.y, acc[5]);
            acc[6] = fmaf(xv, w1.z, acc[6]);
            acc[7] = fmaf(xv, w1.w, acc[7]);
        }
        #pragma unroll
        for (int off = 16; off > 0; off >>= 1) {
            #pragma unroll
            for (int j = 0; j < 8; j++)
                acc[j] += __shfl_down_sync(0xffffffffu, acc[j], off);
        }
        if (lane == 0) {
            float m = acc[0];
            #pragma unroll
            for (int j = 1; j < 8; j++) m = fmaxf(m, acc[j]);
            float e[8], s = 0.f;
            #pragma unroll
            for (int j = 0; j < 8; j++) { e[j] = expf(acc[j] - m); s += e[j]; }
            float inv = 1.f / s;
            float* gp = g_gates + ((size_t)t * BATCH + (b0 + row)) * 8;
            #pragma unroll
            for (int j = 0; j < 8; j++) gp[j] = e[j] * inv;
        }
    }
}

// ---------------------------------------------------------------------------
// K2: expert GEMM. 128x128 CTA tile, K=64 stages, 3-stage full/empty mbarrier
// pipeline (no in-loop CTA barrier), 8 warps (2m x 4n), 64x32 warp tiles,
// 2 CTAs/SM. Stage: A 16KB + B 16KB.
// mbarriers: full[0..2] @SMEM_MBAR, empty[0..2] @SMEM_MBAR+24.
// ---------------------------------------------------------------------------
#define STAGE_B   32768
#define SMEM_MBAR (3 * STAGE_B)            // 98304
#define SMEM_BIAS (SMEM_MBAR + 64)         // 98368
#define SMEM_GEMM (SMEM_BIAS + 512)        // 98880

__global__ __launch_bounds__(256, 2) void expert_gemm_f16(const float* __restrict__ bs,
                                                          const float* __restrict__ bt)
{
    extern __shared__ char smem[];
    const uint32_t sbase = smem_u32(smem);
    float* biassm = (float*)(smem + SMEM_BIAS);
    const uint32_t mb_full  = sbase + SMEM_MBAR;
    const uint32_t mb_empty = sbase + SMEM_MBAR + 24;

    const int tid  = threadIdx.x;
    const int w    = tid >> 5;
    const int lane = tid & 31;
    const int gid  = lane >> 2;
    const int tig  = lane & 3;
    const int warp_m = (w >> 2) * 64;   // 0,64
    const int warp_n = (w & 3) * 32;    // 0,32,64,96

    const int e  = blockIdx.z;
    const int nb = blockIdx.x;          // 0..7
    const int mb = blockIdx.y;          // 0..63
    const int n0 = nb * 128;
    const int m0 = mb * 128;

    const unsigned char* Ax = g_xp + (size_t)mb * 32 * TILE_B;
    const unsigned char* Bw = g_wp + ((size_t)e * 8 + nb) * 32 * TILE_B;
    const float* bias = (e < 4) ? bs + (size_t)e * HD : bt + (size_t)(e - 4) * HD;
    __half* Y = g_yh + (size_t)e * BATCH * HD;

    if (tid < 128) biassm[tid] = bias[n0 + tid];

    // swizzled ldsm lane offsets within a stage
    uint32_t off_a[4][2], off_b[2][2];
    {
        const int hi_a = lane >> 4;
        #pragma unroll
        for (int mi = 0; mi < 4; mi++) {
            const int row = warp_m + mi * 16 + (lane & 7) + ((lane >> 3) & 1) * 8;
            const int sw  = (row >> 1) & 3;
            #pragma unroll
            for (int ks = 0; ks < 2; ks++)
                off_a[mi][ks] = (uint32_t)(row * 64 + (((ks * 2 + hi_a) ^ sw) << 4));
        }
        const int hi_b = (lane >> 3) & 1;
        #pragma unroll
        for (int g = 0; g < 2; g++) {
            const int row = warp_n + g * 16 + (lane & 7) + (lane >> 4) * 8;
            const int sw  = (row >> 1) & 3;
            #pragma unroll
            for (int ks = 0; ks < 2; ks++)
                off_b[g][ks] = (uint32_t)(2 * TILE_B + row * 64
                                          + (((ks * 2 + hi_b) ^ sw) << 4));
        }
    }

    float c[4][4][4];
    #pragma unroll
    for (int mi = 0; mi < 4; mi++)
        #pragma unroll
        for (int ni = 0; ni < 4; ni++)
            #pragma unroll
            for (int r = 0; r < 4; r++) c[mi][ni][r] = 0.f;

    // init: full count=1 (tx-based), empty count=8 (one arrive per warp)
    if (tid == 0) {
        #pragma unroll
        for (int s = 0; s < 3; s++) {
            MBARRIER_INIT(mb_full  + s * 8, 1);
            MBARRIER_INIT(mb_empty + s * 8, 8);
        }
    }
    __syncthreads();   // mbarriers + biassm visible

    if (tid == 0) {
        #pragma unroll
        for (int p = 0; p < 2; p++) {
            const uint32_t mbar = mb_full + p * 8;
            MBARRIER_EXPECT_TX(mbar, STAGE_B);
            bulk_g2s(sbase + p * STAGE_B,              Ax + (size_t)p * 2 * TILE_B,
                     2 * TILE_B, mbar);
            bulk_g2s(sbase + p * STAGE_B + 2 * TILE_B, Bw + (size_t)p * 2 * TILE_B,
                     2 * TILE_B, mbar);
        }
    }

    int cs = 0, cph = 0;      // compute cursor (stage, parity)

    for (int kt = 0; kt < 16; kt++) {
        // producer: load tile kt+2 into stage ls=(kt+2)%3, after its last
        // consumer (tile kt-1) has fully arrived on empty[ls].
        if (tid == 0 && kt + 2 < 16) {
            const int p  = kt + 2;
            const int ls = p - (p / 3) * 3;                 // (kt+2)%3
            if (kt >= 1)
                MBARRIER_WAIT_PARITY(mb_empty + ls * 8, ((kt - 1) / 3) & 1);
            const uint32_t mbar = mb_full + ls * 8;
            MBARRIER_EXPECT_TX(mbar, STAGE_B);
            bulk_g2s(sbase + ls * STAGE_B,              Ax + (size_t)p * 2 * TILE_B,
                     2 * TILE_B, mbar);
            bulk_g2s(sbase + ls * STAGE_B + 2 * TILE_B, Bw + (size_t)p * 2 * TILE_B,
                     2 * TILE_B, mbar);
        }

        MBARRIER_WAIT_PARITY(mb_full + cs * 8, cph);

        const uint32_t stage = sbase + (uint32_t)cs * STAGE_B;
        #pragma unroll
        for (int ks = 0; ks < 4; ks++) {
            const uint32_t sub = (uint32_t)((ks >> 1) * TILE_B);
            uint32_t a[4][4];
            #pragma unroll
            for (int mi = 0; mi < 4; mi++)
                ldsm_x4(a[mi], stage + sub + off_a[mi][ks & 1]);
            uint32_t b[4][2];
            {
                uint32_t r[4];
                ldsm_x4(r, stage + sub + off_b[0][ks & 1]);    // n 0..15
                b[0][0] = r[0]; b[0][1] = r[1]; b[1][0] = r[2]; b[1][1] = r[3];
                ldsm_x4(r, stage + sub + off_b[1][ks & 1]);    // n 16..31
                b[2][0] = r[0]; b[2][1] = r[1]; b[3][0] = r[2]; b[3][1] = r[3];
            }
            #pragma unroll
            for (int mi = 0; mi < 4; mi++)
                #pragma unroll
                for (int ni = 0; ni < 4; ni++)
                    mma_f16(c[mi][ni], a[mi], b[ni]);
        }

        if (lane == 0) MBARRIER_ARRIVE(mb_empty + cs * 8);   // warp done with stage

        if (++cs == 3) { cs = 0; cph ^= 1; }
    }

    // epilogue: bias + relu -> fp16 stores (accumulators are warp-private)
    #pragma unroll
    for (int mi = 0; mi < 4; mi++) {
        #pragma unroll
        for (int ni = 0; ni < 4; ni++) {
            const int rbase = m0 + warp_m + mi * 16 + gid;
            const int col   = warp_n + ni * 8 + 2 * tig;
            const float b0 = biassm[col], b1 = biassm[col + 1];
            __half2 p0 = __floats2half2_rn(fmaxf(c[mi][ni][0] + b0, 0.f),
                                           fmaxf(c[mi][ni][1] + b1, 0.f));
            __half2 p1 = __floats2half2_rn(fmaxf(c[mi][ni][2] + b0, 0.f),
                                           fmaxf(c[mi][ni][3] + b1, 0.f));
            *(__half2*)(Y + (size_t)rbase * HD + n0 + col)       = p0;
            *(__half2*)(Y + (size_t)(rbase + 8) * HD + n0 + col) = p1;
        }
    }
}

// ---------------------------------------------------------------------------
// K3: gated mixture — all 3 tasks per thread
// ---------------------------------------------------------------------------
__global__ __launch_bounds__(256) void mix_kernel(float* __restrict__ out)
{
    const size_t idx = (size_t)blockIdx.x * blockDim.x + threadIdx.x;
    const int h4 = (int)(idx & 255);
    const int b  = (int)(idx >> 8);

    float g[NTASK][8];
    #pragma unroll
    for (int t = 0; t < NTASK; t++) {
        const float4* gp = (const float4*)(g_gates + ((size_t)t * BATCH + b) * 8);
        float4 g0 = gp[0], g1 = gp[1];
        g[t][0] = g0.x; g[t][1] = g0.y; g[t][2] = g0.z; g[t][3] = g0.w;
        g[t][4] = g1.x; g[t][5] = g1.y; g[t][6] = g1.z; g[t][7] = g1.w;
    }

    float4 acc[NTASK];
    #pragma unroll
    for (int t = 0; t < NTASK; t++) acc[t] = make_float4(0.f, 0.f, 0.f, 0.f);

    #pragma unroll
    for (int j = 0; j < 4; j++) {    // shared experts -> all tasks (slot 4+j)
        const uint2 v = *(const uint2*)(g_yh + ((size_t)j * BATCH + b) * HD + (size_t)h4 * 4);
        const float2 f01 = __half22float2(*(const __half2*)&v.x);
        const float2 f23 = __half22float2(*(const __half2*)&v.y);
        #pragma unroll
        for (int t = 0; t < NTASK; t++) {
            const float gv = g[t][4 + j];
            acc[t].x = fmaf(gv, f01.x, acc[t].x);
            acc[t].y = fmaf(gv, f01.y, acc[t].y);
            acc[t].z = fmaf(gv, f23.x, acc[t].z);
            acc[t].w = fmaf(gv, f23.y, acc[t].w);
        }
    }
    #pragma unroll
    for (int t = 0; t < NTASK; t++) {   // task-specific experts (slot j)
        #pragma unroll
        for (int j = 0; j < 4; j++) {
            const int ei = 4 + t * 4 + j;
            const uint2 v = *(const uint2*)(g_yh + ((size_t)ei * BATCH + b) * HD + (size_t)h4 * 4);
            const float2 f01 = __half22float2(*(const __half2*)&v.x);
            const float2 f23 = __half22float2(*(const __half2*)&v.y);
            const float gv = g[t][j];
            acc[t].x = fmaf(gv, f01.x, acc[t].x);
            acc[t].y = fmaf(gv, f01.y, acc[t].y);
            acc[t].z = fmaf(gv, f23.x, acc[t].z);
            acc[t].w = fmaf(gv, f23.y, acc[t].w);
        }
    }

    #pragma unroll
    for (int t = 0; t < NTASK; t++)
        *(float4*)(out + ((size_t)t * BATCH + b) * HD + (size_t)h4 * 4) = acc[t];
}

// ---------------------------------------------------------------------------
extern "C" void kernel_launch(void* const* d_in, const int* in_sizes, int n_in,
                              void* d_out, int out_size)
{
    (void)in_sizes; (void)n_in; (void)out_size;
    const float* x  = (const float*)d_in[0];
    const float* Ws = (const float*)d_in[1];
    const float* bs = (const float*)d_in[2];
    const float* Wt = (const float*)d_in[3];
    const float* bt = (const float*)d_in[4];
    const float* Wg = (const float*)d_in[5];
    float* out = (float*)d_out;

    cudaFuncSetAttribute(expert_gemm_f16,
                         cudaFuncAttributeMaxDynamicSharedMemorySize, SMEM_GEMM);
    cudaFuncSetAttribute(gate_kernel,
                         cudaFuncAttributeMaxDynamicSharedMemorySize, GATE_SMEM);

    pack_x<<<4096, 256>>>(x);
    pack_w<<<dim3(32, 32, 16), 256>>>(Ws, Wt);
    gate_kernel<<<BATCH / GATE_ROWS, 256, GATE_SMEM>>>(x, Wg);
    expert_gemm_f16<<<dim3(8, 64, 16), 256, SMEM_GEMM>>>(bs, bt);

    const size_t nthreads = (size_t)BATCH * (HD / 4);
    mix_kernel<<<(unsigned)(nthreads / 256), 256>>>(out);
}